// round 5
// baseline (speedup 1.0000x reference)
#include <cuda_runtime.h>
#include <math_constants.h>

// CollectNeighbourAverageAndMax: V=100000, K=32, F=64
// out[v, 0:64]   = sum_k x[idxs[v,k], :] / K
// out[v, 64:128] = max_k x[idxs[v,k], :]
//
// Warp per vertex; per instruction, LDG.128 gathers TWO neighbor rows:
//   lanes 0-15  -> neighbor 2kp,   float4 of features [4hl..4hl+3]
//   lanes 16-31 -> neighbor 2kp+1, same features
// Halves keep separate partials (even-k in low half, odd-k in high half);
// a shfl.bfly(16) combine at the end merges them, then ONE STG.128 writes
// mean (low half) and max (high half) — 512B contiguous across the warp.
// Memory instructions per vertex: 37 -> 18 at identical wavefront count,
// cutting LSU dispatch pressure (the co-limiter with wavefront service).

static constexpr int V = 100000;
static constexpr int K = 32;
static constexpr int F = 64;

__global__ __launch_bounds__(256) void collect_nb_kernel(
    const float* __restrict__ x,
    const int* __restrict__ idxs,
    float* __restrict__ out)
{
    const int warp_id = (blockIdx.x * blockDim.x + threadIdx.x) >> 5;
    const int lane = threadIdx.x & 31;
    if (warp_id >= V) return;

    const int hsel = lane >> 4;    // 0 = low half (even k), 1 = high half (odd k)
    const int hl   = lane & 15;    // lane within half-warp

    // Coalesced index load; pre-scale to row offset (idx * F).
    const int my_row = idxs[warp_id * K + lane] * F;

    float4 s = make_float4(0.f, 0.f, 0.f, 0.f);
    float4 m = make_float4(-CUDART_INF_F, -CUDART_INF_F, -CUDART_INF_F, -CUDART_INF_F);

    const float* xb = x + 4 * hl;  // this lane's feature offset within a row

    #pragma unroll
    for (int kp = 0; kp < K / 2; ++kp) {
        // low half fetches neighbor 2kp, high half fetches neighbor 2kp+1
        const int row = __shfl_sync(0xffffffffu, my_row, 2 * kp + hsel);
        const float4 r = *reinterpret_cast<const float4*>(xb + row);
        s.x += r.x; s.y += r.y; s.z += r.z; s.w += r.w;
        m.x = fmaxf(m.x, r.x); m.y = fmaxf(m.y, r.y);
        m.z = fmaxf(m.z, r.z); m.w = fmaxf(m.w, r.w);
    }

    // Combine even/odd partials across the two halves.
    s.x += __shfl_xor_sync(0xffffffffu, s.x, 16);
    s.y += __shfl_xor_sync(0xffffffffu, s.y, 16);
    s.z += __shfl_xor_sync(0xffffffffu, s.z, 16);
    s.w += __shfl_xor_sync(0xffffffffu, s.w, 16);
    m.x = fmaxf(m.x, __shfl_xor_sync(0xffffffffu, m.x, 16));
    m.y = fmaxf(m.y, __shfl_xor_sync(0xffffffffu, m.y, 16));
    m.z = fmaxf(m.z, __shfl_xor_sync(0xffffffffu, m.z, 16));
    m.w = fmaxf(m.w, __shfl_xor_sync(0xffffffffu, m.w, 16));

    constexpr float inv_k = 1.0f / K;
    // Low half stores the mean block, high half stores the max block:
    // addresses are contiguous 512B across the warp -> one STG.128.
    float4 o_val;
    if (hsel == 0) {
        o_val = make_float4(s.x * inv_k, s.y * inv_k, s.z * inv_k, s.w * inv_k);
    } else {
        o_val = m;
    }
    float* o = out + (size_t)warp_id * (2 * F) + hsel * F + 4 * hl;
    *reinterpret_cast<float4*>(o) = o_val;
}

extern "C" void kernel_launch(void* const* d_in, const int* in_sizes, int n_in,
                              void* d_out, int out_size)
{
    const float* x = (const float*)d_in[0];
    const int* idxs = (const int*)d_in[1];
    float* out = (float*)d_out;

    const int threads = 256;                  // 8 warps -> 8 vertices per block
    const int warps_per_block = threads / 32;
    const int blocks = (V + warps_per_block - 1) / warps_per_block;  // 12500

    collect_nb_kernel<<<blocks, threads>>>(x, idxs, out);
}